// round 2
// baseline (speedup 1.0000x reference)
#include <cuda_runtime.h>

#define B   8
#define N   2048
#define D   1024
#define E   8
#define CAP 320
#define NT  (B * N)

// Scratch (device allocations are forbidden -> __device__ globals)
__device__ int   g_e1[NT];
__device__ int   g_e2[NT];
__device__ float g_g1[NT];
__device__ float g_g2[NT];
__device__ int   g_m2[NT];
__device__ int   g_pos1[NT];   // flat offset within token row is derived later
__device__ int   g_pos2[NT];

// ---------------------------------------------------------------------------
// Kernel 1: logits (warp-per-token GEMV), softmax, top-1/top-2, normalization
// ---------------------------------------------------------------------------
__global__ __launch_bounds__(256) void gating_kernel(const float* __restrict__ x,
                                                     const float* __restrict__ W) {
    // W is [D, E] row-major; transpose into smem as Wt[e][d] so consecutive
    // lanes read consecutive 16B chunks of one expert row (conflict-free LDS.128).
    __shared__ float Wt[E * D];
    int tid = threadIdx.x;
    for (int idx = tid; idx < D * E; idx += 256) {
        int d = idx >> 3;
        int e = idx & 7;
        Wt[e * D + d] = W[idx];
    }
    __syncthreads();

    int warp  = tid >> 5;
    int lane  = tid & 31;
    int token = blockIdx.x * 8 + warp;

    const float4* xv = reinterpret_cast<const float4*>(x + (size_t)token * D);

    float acc[E];
#pragma unroll
    for (int e = 0; e < E; e++) acc[e] = 0.0f;

#pragma unroll
    for (int it = 0; it < 8; it++) {
        int q = it * 32 + lane;            // float4 index within the token (256 total)
        float4 xf = xv[q];
        int d0 = q * 4;
#pragma unroll
        for (int e = 0; e < E; e++) {
            float4 wf = *reinterpret_cast<const float4*>(&Wt[e * D + d0]);
            acc[e] += xf.x * wf.x + xf.y * wf.y + xf.z * wf.z + xf.w * wf.w;
        }
    }

    // warp tree-reduce the 8 expert logits
#pragma unroll
    for (int e = 0; e < E; e++) {
#pragma unroll
        for (int o = 16; o > 0; o >>= 1)
            acc[e] += __shfl_xor_sync(0xffffffffu, acc[e], o);
    }

    if (lane == 0) {
        // softmax over 8 gates
        float m = acc[0];
#pragma unroll
        for (int e = 1; e < E; e++) m = fmaxf(m, acc[e]);
        float p[E];
        float s = 0.0f;
#pragma unroll
        for (int e = 0; e < E; e++) { p[e] = expf(acc[e] - m); s += p[e]; }
        float inv = 1.0f / s;

        // top-1 (first-index tie-break, matching jnp.argmax; exp is monotonic)
        int e1 = 0; float g1 = p[0];
#pragma unroll
        for (int e = 1; e < E; e++) if (p[e] > g1) { g1 = p[e]; e1 = e; }
        // top-2 over the remaining gates
        int e2 = 0; float g2 = -1.0f;
#pragma unroll
        for (int e = 0; e < E; e++)
            if (e != e1 && p[e] > g2) { g2 = p[e]; e2 = e; }
        g1 *= inv;
        g2 *= inv;

        // faithful to the reference's order of operations: g1 is normalized
        // first and the UPDATED g1 feeds g2's denominator.
        float g1n = g1 / (g1 + g2 + 1e-9f);
        float g2n = g2 / (g1n + g2 + 1e-9f);

        g_e1[token] = e1;
        g_e2[token] = e2;
        g_g1[token] = g1n;
        g_g2[token] = g2n;
        g_m2[token] = (g2n > 0.2f) ? 1 : 0;
        g_pos2[token] = -1;          // default: token not routed to 2nd expert
        g_pos1[token] = -1;          // overwritten by scan unless dropped
    }
}

// ---------------------------------------------------------------------------
// Kernel 2: per-(batch, expert) exclusive running prefix over tokens via
// ballot/popc. One warp per (b, e): 8 blocks x 8 warps. ~KB-scale traffic.
// ---------------------------------------------------------------------------
__global__ __launch_bounds__(256) void scan_kernel() {
    int b    = blockIdx.x;
    int eid  = threadIdx.x >> 5;
    int lane = threadIdx.x & 31;
    unsigned lmask = (1u << lane) - 1u;
    int base = b * N;

    // pass 1: top-1 positions + capacity
    int run = 0;
#pragma unroll 4
    for (int it = 0; it < N / 32; it++) {
        int t = base + it * 32 + lane;
        bool m = (g_e1[t] == eid);
        unsigned bal = __ballot_sync(0xffffffffu, m);
        if (m) {
            int pos = run + __popc(bal & lmask);
            g_pos1[t] = (pos < CAP) ? pos : -1;
        }
        run += __popc(bal);
    }
    int c1 = min(run, CAP);      // mask_1_count after capacity clamp

    // pass 2: thresholded top-2 positions, offset by retained top-1 count
    int run2 = 0;
#pragma unroll 4
    for (int it = 0; it < N / 32; it++) {
        int t = base + it * 32 + lane;
        bool m = (g_e2[t] == eid) && (g_m2[t] != 0);
        unsigned bal = __ballot_sync(0xffffffffu, m);
        if (m) {
            int pos = c1 + run2 + __popc(bal & lmask);
            g_pos2[t] = (pos < CAP) ? pos : -1;
        }
        run2 += __popc(bal);
    }
}

// ---------------------------------------------------------------------------
// Kernel 3: fused zero-fill + scatter. One block per token writes the full
// [E, CAP] = 2560-float row as streaming float4 stores, splicing in the
// <=2 nonzero gate values. Single 168MB write pass, no partial-line stores.
// ---------------------------------------------------------------------------
#define ROW   (E * CAP)          // 2560 floats = 640 float4
#define FILLT 256

__global__ __launch_bounds__(FILLT) void fill_kernel(float* __restrict__ out) {
    int t = blockIdx.x;

    // broadcast the token's routing via L2/L1 (same addresses for all threads)
    int   p1 = g_pos1[t];
    int   p2 = g_pos2[t];
    int   o1 = (p1 >= 0) ? (g_e1[t] * CAP + p1) : -4;   // -4: never matches
    int   o2 = (p2 >= 0) ? (g_e2[t] * CAP + p2) : -4;
    float v1 = g_g1[t];
    float v2 = g_g2[t];

    float4* row = reinterpret_cast<float4*>(out + (size_t)t * ROW);

#pragma unroll
    for (int it = 0; it < ROW / 4 / FILLT + 1; it++) {   // 640/256 -> 3 iters (2.5)
        int q = it * FILLT + threadIdx.x;                // float4 index in row
        if (q < ROW / 4) {
            int c = q * 4;
            float4 v = make_float4(0.f, 0.f, 0.f, 0.f);
            int d1 = o1 - c;
            if ((unsigned)d1 < 4u) ((float*)&v)[d1] = v1;
            int d2 = o2 - c;
            if ((unsigned)d2 < 4u) ((float*)&v)[d2] = v2;
            row[q] = v;
        }
    }
}

// ---------------------------------------------------------------------------
extern "C" void kernel_launch(void* const* d_in, const int* in_sizes, int n_in,
                              void* d_out, int out_size) {
    const float* x = (const float*)d_in[0];   // [8, 2048, 1024] f32
    const float* W = (const float*)d_in[1];   // [1024, 8] f32
    float* out = (float*)d_out;               // [8, 2048, 8, 320] f32

    gating_kernel<<<NT / 8, 256>>>(x, W);
    scan_kernel<<<B, 256>>>();
    fill_kernel<<<NT, FILLT>>>(out);
}

// round 17
// speedup vs baseline: 1.1331x; 1.1331x over previous
#include <cuda_runtime.h>

#define B   8
#define N   2048
#define D   1024
#define E   8
#define CAP 320
#define NT  (B * N)
#define ROW (E * CAP)            // 2560 floats = 640 float4 per token

// Scratch (device allocations are forbidden -> __device__ globals)
__device__ int  g_e1[NT];
__device__ int  g_e2[NT];
__device__ int  g_m2[NT];
// packed per-token routing for the fill pass: {o1, o2, v1bits, v2bits}
// o = e*CAP + pos, or -4 if the token writes nothing for that expert slot
__device__ int4 g_pack[NT];

// ---------------------------------------------------------------------------
// Kernel 1: logits GEMV with 4 tokens per warp (each W LDS.128 feeds 4 tokens
// -> 3x less L1 traffic per token than 1-token-per-warp), then softmax/top-2.
// ---------------------------------------------------------------------------
__global__ __launch_bounds__(256) void gating_kernel(const float* __restrict__ x,
                                                     const float* __restrict__ W) {
    // W is [D, E] row-major; transpose into smem as Wt[e][d] so one LDS.128
    // per (expert, d-chunk) is conflict-free across lanes.
    __shared__ float Wt[E * D];
    int tid = threadIdx.x;
    for (int idx = tid; idx < D * E; idx += 256) {
        int d = idx >> 3;
        int e = idx & 7;
        Wt[e * D + d] = W[idx];
    }
    __syncthreads();

    int warp  = tid >> 5;
    int lane  = tid & 31;
    int tbase = blockIdx.x * 32 + warp * 4;      // 4 tokens per warp

    const float4* xv0 = reinterpret_cast<const float4*>(x + (size_t)(tbase + 0) * D);
    const float4* xv1 = reinterpret_cast<const float4*>(x + (size_t)(tbase + 1) * D);
    const float4* xv2 = reinterpret_cast<const float4*>(x + (size_t)(tbase + 2) * D);
    const float4* xv3 = reinterpret_cast<const float4*>(x + (size_t)(tbase + 3) * D);

    float acc[4][E];
#pragma unroll
    for (int k = 0; k < 4; k++)
#pragma unroll
        for (int e = 0; e < E; e++) acc[k][e] = 0.0f;

#pragma unroll
    for (int it = 0; it < 8; it++) {
        int q  = it * 32 + lane;                 // float4 index within token (256)
        int d0 = q * 4;
        float4 xf0 = xv0[q];
        float4 xf1 = xv1[q];
        float4 xf2 = xv2[q];
        float4 xf3 = xv3[q];
#pragma unroll
        for (int e = 0; e < E; e++) {
            float4 wf = *reinterpret_cast<const float4*>(&Wt[e * D + d0]);
            acc[0][e] += xf0.x * wf.x + xf0.y * wf.y + xf0.z * wf.z + xf0.w * wf.w;
            acc[1][e] += xf1.x * wf.x + xf1.y * wf.y + xf1.z * wf.z + xf1.w * wf.w;
            acc[2][e] += xf2.x * wf.x + xf2.y * wf.y + xf2.z * wf.z + xf2.w * wf.w;
            acc[3][e] += xf3.x * wf.x + xf3.y * wf.y + xf3.z * wf.z + xf3.w * wf.w;
        }
    }

    // tree-reduce all 32 accumulators across the warp (result on all lanes)
#pragma unroll
    for (int k = 0; k < 4; k++)
#pragma unroll
        for (int e = 0; e < E; e++)
#pragma unroll
            for (int o = 16; o > 0; o >>= 1)
                acc[k][e] += __shfl_xor_sync(0xffffffffu, acc[k][e], o);

    // lanes 0..3 each finish one token (softmax + top-2 + normalization)
    if (lane < 4) {
        int   token = tbase + lane;
        float l[E];
#pragma unroll
        for (int e = 0; e < E; e++) l[e] = acc[lane][e];

        float m = l[0];
#pragma unroll
        for (int e = 1; e < E; e++) m = fmaxf(m, l[e]);
        float p[E];
        float s = 0.0f;
#pragma unroll
        for (int e = 0; e < E; e++) { p[e] = expf(l[e] - m); s += p[e]; }
        float inv = 1.0f / s;

        // top-1 (first-index tie-break, matching jnp.argmax; exp is monotonic)
        int e1 = 0; float g1 = p[0];
#pragma unroll
        for (int e = 1; e < E; e++) if (p[e] > g1) { g1 = p[e]; e1 = e; }
        // top-2 over remaining gates
        int e2 = 0; float g2 = -1.0f;
#pragma unroll
        for (int e = 0; e < E; e++)
            if (e != e1 && p[e] > g2) { g2 = p[e]; e2 = e; }
        g1 *= inv;
        g2 *= inv;

        // faithful to the reference's ordering: updated g1 feeds g2's denominator
        float g1n = g1 / (g1 + g2 + 1e-9f);
        float g2n = g2 / (g1n + g2 + 1e-9f);

        g_e1[token] = e1;
        g_e2[token] = e2;
        g_m2[token] = (g2n > 0.2f) ? 1 : 0;
        g_pack[token] = make_int4(-4, -4, __float_as_int(g1n), __float_as_int(g2n));
    }
}

// ---------------------------------------------------------------------------
// Kernel 2: per-(batch, expert) running exclusive prefix via ballot/popc.
// One warp per (b, e): 8 blocks x 8 warps. Writes packed offsets into g_pack.
// ---------------------------------------------------------------------------
__global__ __launch_bounds__(256) void scan_kernel() {
    int b    = blockIdx.x;
    int eid  = threadIdx.x >> 5;
    int lane = threadIdx.x & 31;
    unsigned lmask = (1u << lane) - 1u;
    int base = b * N;

    // pass 1: top-1 positions + capacity (exactly one warp matches each token)
    int run = 0;
#pragma unroll 4
    for (int it = 0; it < N / 32; it++) {
        int t = base + it * 32 + lane;
        bool m = (g_e1[t] == eid);
        unsigned bal = __ballot_sync(0xffffffffu, m);
        if (m) {
            int pos = run + __popc(bal & lmask);
            reinterpret_cast<int*>(&g_pack[t])[0] =
                (pos < CAP) ? (eid * CAP + pos) : -4;
        }
        run += __popc(bal);
    }
    int c1 = min(run, CAP);      // mask_1_count after capacity clamp

    // pass 2: thresholded top-2 positions, offset by retained top-1 count
    int run2 = 0;
#pragma unroll 4
    for (int it = 0; it < N / 32; it++) {
        int t = base + it * 32 + lane;
        bool m = (g_e2[t] == eid) && (g_m2[t] != 0);
        unsigned bal = __ballot_sync(0xffffffffu, m);
        if (m) {
            int pos = c1 + run2 + __popc(bal & lmask);
            reinterpret_cast<int*>(&g_pack[t])[1] =
                (pos < CAP) ? (eid * CAP + pos) : -4;
        }
        run2 += __popc(bal);
    }
}

// ---------------------------------------------------------------------------
// Kernel 3: fused zero-fill + scatter, persistent grid-stride over tokens.
// 128 threads/block -> 640 float4 per token = exactly 5 per thread (no
// predication). One broadcast LDG.128 of routing per token. Streaming (.cs)
// stores: output is write-once, never re-read by the kernel chain.
// ---------------------------------------------------------------------------
#define FILL_BLOCKS 2368         // 148 SMs x 16 blocks: single wave

__global__ __launch_bounds__(128) void fill_kernel(float* __restrict__ out) {
    int tid = threadIdx.x;
    for (int t = blockIdx.x; t < NT; t += FILL_BLOCKS) {
        int4  pk = g_pack[t];                    // broadcast load
        float v1 = __int_as_float(pk.z);
        float v2 = __int_as_float(pk.w);
        float4* row = reinterpret_cast<float4*>(out + (size_t)t * ROW) + tid;
#pragma unroll
        for (int i = 0; i < 5; i++) {
            int q = i * 128 + tid;               // float4 index in row
            int c = q * 4;
            float4 v = make_float4(0.f, 0.f, 0.f, 0.f);
            int d1 = pk.x - c;
            if ((unsigned)d1 < 4u) reinterpret_cast<float*>(&v)[d1] = v1;
            int d2 = pk.y - c;
            if ((unsigned)d2 < 4u) reinterpret_cast<float*>(&v)[d2] = v2;
            __stcs(row + i * 128, v);            // STG.E.128 .cs (evict-first)
        }
    }
}

// ---------------------------------------------------------------------------
extern "C" void kernel_launch(void* const* d_in, const int* in_sizes, int n_in,
                              void* d_out, int out_size) {
    const float* x = (const float*)d_in[0];   // [8, 2048, 1024] f32
    const float* W = (const float*)d_in[1];   // [1024, 8] f32
    float* out = (float*)d_out;               // [8, 2048, 8, 320] f32

    gating_kernel<<<NT / 32, 256>>>(x, W);
    scan_kernel<<<B, 256>>>();
    fill_kernel<<<FILL_BLOCKS, 128>>>(out);
}